// round 3
// baseline (speedup 1.0000x reference)
#include <cuda_runtime.h>
#include <cuda_bf16.h>
#include <math.h>

// Problem constants
#define NN   50000
#define EE   800000
#define FDIM 128
#define HDIM 64
#define LL   3
#define GG   256
#define CC   10
#define TCOLS 384   // 6 blocks of 64: [W2hom|W2het|W1hom|W1het|W0hom|W0het]

// ---------------- scratch (__device__ globals; no allocation allowed) ----------------
__device__ float g_T[(size_t)NN * TCOLS];     // per-layer GEMM output [N,384]
__device__ float g_h[(size_t)NN * FDIM];      // node features [N,128] (hom|het)
__device__ float g_u[(size_t)NN * FDIM];      // hop scratch [N,128] (hom|het)
__device__ float g_Wcat[LL * FDIM * TCOLS];   // packed weights, all layers

__device__ int    g_cnt[NN];
__device__ int    g_fill[NN];
__device__ int    g_rowptr[NN + 1];
__device__ int    g_csr_src[EE];
__device__ float2 g_csr_mask[EE];             // (hom, het)
__device__ float  g_deg_hom[NN];
__device__ float  g_deg_het[NN];
__device__ int    g_gptr[GG + 1];
__device__ float  g_r[GG * 4 * HDIM];         // readout accumulator [G,256]

// ---------------- CSR build ----------------
__global__ void init_zero_kernel() {
    int i = blockIdx.x * blockDim.x + threadIdx.x;
    if (i < NN) {
        g_cnt[i] = 0;
        g_deg_hom[i] = 0.f;
        g_deg_het[i] = 0.f;
    }
}

__global__ void count_kernel(const int* __restrict__ ei,
                             const float* __restrict__ hm,
                             const float* __restrict__ tm) {
    int e = blockIdx.x * blockDim.x + threadIdx.x;
    if (e >= EE) return;
    int d = ei[EE + e];             // dst row of edge_index
    atomicAdd(&g_cnt[d], 1);
    atomicAdd(&g_deg_hom[d], hm[e]);
    atomicAdd(&g_deg_het[d], tm[e]);
}

__global__ void scan_kernel() {
    __shared__ int s[1024];
    const int t = threadIdx.x;
    const int CH = (NN + 1023) / 1024;
    int base = t * CH;
    int sum = 0;
    for (int i = 0; i < CH; i++) {
        int idx = base + i;
        if (idx < NN) sum += g_cnt[idx];
    }
    s[t] = sum;
    __syncthreads();
    for (int off = 1; off < 1024; off <<= 1) {
        int v = 0;
        if (t >= off) v = s[t - off];
        __syncthreads();
        if (t >= off) s[t] += v;
        __syncthreads();
    }
    int run = (t == 0) ? 0 : s[t - 1];
    for (int i = 0; i < CH; i++) {
        int idx = base + i;
        if (idx < NN) {
            int c = g_cnt[idx];
            g_rowptr[idx] = run;
            g_fill[idx] = run;
            run += c;
        }
    }
    if (t == 1023) g_rowptr[NN] = run;
}

__global__ void scatter_kernel(const int* __restrict__ ei,
                               const float* __restrict__ hm,
                               const float* __restrict__ tm) {
    int e = blockIdx.x * blockDim.x + threadIdx.x;
    if (e >= EE) return;
    int d = ei[EE + e];
    int p = atomicAdd(&g_fill[d], 1);
    g_csr_src[p] = ei[e];
    g_csr_mask[p] = make_float2(hm[e], tm[e]);
}

__global__ void gptr_kernel(const int* __restrict__ batch) {
    int n = blockIdx.x * blockDim.x + threadIdx.x;
    if (n >= NN) return;
    int b = batch[n];
    int prev = (n == 0) ? -1 : batch[n - 1];
    for (int g = prev + 1; g <= b; ++g) g_gptr[g] = n;
    if (n == NN - 1) {
        for (int g = b + 1; g <= GG; ++g) g_gptr[g] = NN;
    }
}

// ---------------- pack all layers' weights into [L][128][384] ----------------
// column block b (of 6 x 64): view = b&1 (0 hom), hop j = 2 - b/2
__global__ void packW_all_kernel(const float* __restrict__ homW,
                                 const float* __restrict__ hetW) {
    int idx = blockIdx.x * blockDim.x + threadIdx.x;
    if (idx >= LL * FDIM * TCOLS) return;
    int l = idx / (FDIM * TCOLS);
    int rem = idx % (FDIM * TCOLS);
    int k = rem / TCOLS, c = rem % TCOLS;
    int b = c / HDIM;
    int v = b & 1;
    int j = 2 - (b >> 1);
    int cc = c % HDIM;
    const float* Ws = v ? hetW : homW;
    g_Wcat[idx] = Ws[((size_t)(l * 3 + j) * FDIM + k) * HDIM + cc];
}

// ---------------- 3xTF32 tensor-core GEMM: C[N,384] = A[N,128] @ Wcat[l][128,384] ----------------
// BM=128, BN=128, BK=16. 8 warps: warp tile 64x32 (m16n8k8 grid 4x4).
#define BM 128
#define BN 128
#define BK 16

__device__ __forceinline__ unsigned ftf(float x) {
    unsigned u;
    asm("cvt.rna.tf32.f32 %0, %1;" : "=r"(u) : "f"(x));
    return u;
}
__device__ __forceinline__ float2 split_tf32(float x) {
    unsigned hi = ftf(x);
    float hif = __uint_as_float(hi);
    unsigned lo = ftf(x - hif);
    return make_float2(hif, __uint_as_float(lo));
}

#define MMA_TF32(d, a0, a1, a2, a3, b0, b1)                                     \
    asm volatile(                                                               \
        "mma.sync.aligned.m16n8k8.row.col.f32.tf32.tf32.f32 "                   \
        "{%0,%1,%2,%3}, {%4,%5,%6,%7}, {%8,%9}, {%0,%1,%2,%3};"                 \
        : "+f"(d[0]), "+f"(d[1]), "+f"(d[2]), "+f"(d[3])                        \
        : "r"(a0), "r"(a1), "r"(a2), "r"(a3), "r"(b0), "r"(b1));

__global__ __launch_bounds__(256, 2) void sgemm_tc_kernel(const float* __restrict__ A,
                                                          const float* __restrict__ W,
                                                          float* __restrict__ C, int M) {
    // smem: (hi,lo) float2 per element
    __shared__ float2 As2[BM][BK + 1];   // [row][k]
    __shared__ float2 Bs2[BN][BK + 1];   // [col][k]

    const int tid = threadIdx.x;
    const int wid = tid >> 5;
    const int lane = tid & 31;
    const int g = lane >> 2;       // 0..7
    const int tg = lane & 3;       // 0..3
    const int warpRow = (wid & 1) * 64;
    const int warpCol = (wid >> 1) * 32;
    const int rowBase = blockIdx.y * BM;
    const int colBase = blockIdx.x * BN;

    float acc[4][4][4];
#pragma unroll
    for (int mi = 0; mi < 4; mi++)
#pragma unroll
        for (int ni = 0; ni < 4; ni++)
#pragma unroll
            for (int r = 0; r < 4; r++) acc[mi][ni][r] = 0.f;

    // global load mapping
    const int rowA = tid >> 1;           // 0..127
    const int colA = (tid & 1) * 8;      // 0 or 8
    const int rowB = tid >> 4;           // 0..15
    const int colB = (tid & 15) * 8;     // 0..120

    for (int k0 = 0; k0 < FDIM; k0 += BK) {
        // ---- load + split A tile [BM x BK] ----
        {
            int gr = rowBase + rowA;
            float4 v0 = make_float4(0.f, 0.f, 0.f, 0.f);
            float4 v1 = v0;
            if (gr < M) {
                v0 = *(const float4*)&A[(size_t)gr * FDIM + k0 + colA];
                v1 = *(const float4*)&A[(size_t)gr * FDIM + k0 + colA + 4];
            }
            As2[rowA][colA + 0] = split_tf32(v0.x);
            As2[rowA][colA + 1] = split_tf32(v0.y);
            As2[rowA][colA + 2] = split_tf32(v0.z);
            As2[rowA][colA + 3] = split_tf32(v0.w);
            As2[rowA][colA + 4] = split_tf32(v1.x);
            As2[rowA][colA + 5] = split_tf32(v1.y);
            As2[rowA][colA + 6] = split_tf32(v1.z);
            As2[rowA][colA + 7] = split_tf32(v1.w);
        }
        // ---- load + split B tile [BK x BN] -> Bs2[col][k] ----
        {
            const float* Wr = &W[(size_t)(k0 + rowB) * TCOLS + colBase + colB];
            float4 v0 = *(const float4*)&Wr[0];
            float4 v1 = *(const float4*)&Wr[4];
            Bs2[colB + 0][rowB] = split_tf32(v0.x);
            Bs2[colB + 1][rowB] = split_tf32(v0.y);
            Bs2[colB + 2][rowB] = split_tf32(v0.z);
            Bs2[colB + 3][rowB] = split_tf32(v0.w);
            Bs2[colB + 4][rowB] = split_tf32(v1.x);
            Bs2[colB + 5][rowB] = split_tf32(v1.y);
            Bs2[colB + 6][rowB] = split_tf32(v1.z);
            Bs2[colB + 7][rowB] = split_tf32(v1.w);
        }
        __syncthreads();

#pragma unroll
        for (int ks = 0; ks < BK / 8; ks++) {
            const int kk0 = ks * 8 + tg;
            const int kk1 = kk0 + 4;
            // A fragments (hi & lo)
            unsigned ah[4][4], al[4][4];
#pragma unroll
            for (int mi = 0; mi < 4; mi++) {
                int r0 = warpRow + mi * 16 + g;
                int r1 = r0 + 8;
                float2 p0 = As2[r0][kk0];
                float2 p1 = As2[r1][kk0];
                float2 p2 = As2[r0][kk1];
                float2 p3 = As2[r1][kk1];
                ah[mi][0] = __float_as_uint(p0.x); al[mi][0] = __float_as_uint(p0.y);
                ah[mi][1] = __float_as_uint(p1.x); al[mi][1] = __float_as_uint(p1.y);
                ah[mi][2] = __float_as_uint(p2.x); al[mi][2] = __float_as_uint(p2.y);
                ah[mi][3] = __float_as_uint(p3.x); al[mi][3] = __float_as_uint(p3.y);
            }
#pragma unroll
            for (int ni = 0; ni < 4; ni++) {
                int n = warpCol + ni * 8 + g;
                float2 q0 = Bs2[n][kk0];
                float2 q1 = Bs2[n][kk1];
                unsigned bh0 = __float_as_uint(q0.x), bl0 = __float_as_uint(q0.y);
                unsigned bh1 = __float_as_uint(q1.x), bl1 = __float_as_uint(q1.y);
#pragma unroll
                for (int mi = 0; mi < 4; mi++) {
                    MMA_TF32(acc[mi][ni], ah[mi][0], ah[mi][1], ah[mi][2], ah[mi][3], bh0, bh1);
                    MMA_TF32(acc[mi][ni], al[mi][0], al[mi][1], al[mi][2], al[mi][3], bh0, bh1);
                    MMA_TF32(acc[mi][ni], ah[mi][0], ah[mi][1], ah[mi][2], ah[mi][3], bl0, bl1);
                }
            }
        }
        __syncthreads();
    }

    // epilogue
#pragma unroll
    for (int mi = 0; mi < 4; mi++) {
        int gr0 = rowBase + warpRow + mi * 16 + g;
        int gr1 = gr0 + 8;
#pragma unroll
        for (int ni = 0; ni < 4; ni++) {
            int gc = colBase + warpCol + ni * 8 + tg * 2;
            if (gr0 < M)
                *(float2*)&C[(size_t)gr0 * TCOLS + gc] = make_float2(acc[mi][ni][0], acc[mi][ni][1]);
            if (gr1 < M)
                *(float2*)&C[(size_t)gr1 * TCOLS + gc] = make_float2(acc[mi][ni][2], acc[mi][ni][3]);
        }
    }
}

// ---------------- fused two-view aggregation: one warp per destination node ----------------
__global__ void agg2_kernel(const float* __restrict__ gather, int gld,
                            const float* __restrict__ add, int ald, int acol,
                            const float* __restrict__ hom_b,  // non-null => relu(.+bias)
                            const float* __restrict__ het_b,
                            float* __restrict__ out) {
    int gw = (blockIdx.x * blockDim.x + threadIdx.x) >> 5;
    int lane = threadIdx.x & 31;
    if (gw >= NN) return;
    const bool het = lane >= 16;
    int s = g_rowptr[gw];
    int e = g_rowptr[gw + 1];
    float ax = 0.f, ay = 0.f, az = 0.f, aw = 0.f;
    for (int i = s; i < e; i++) {
        int sr = g_csr_src[i];
        float2 mm = g_csr_mask[i];
        float m = het ? mm.y : mm.x;
        float4 v = *(const float4*)&gather[(size_t)sr * gld + 4 * lane];
        ax = fmaf(m, v.x, ax);
        ay = fmaf(m, v.y, ay);
        az = fmaf(m, v.z, az);
        aw = fmaf(m, v.w, aw);
    }
    float d = fmaxf(het ? g_deg_het[gw] : g_deg_hom[gw], 1.f);
    float inv = 1.f / d;
    float4 a = *(const float4*)&add[(size_t)gw * ald + acol + 4 * lane];
    float ox = fmaf(ax, inv, a.x);
    float oy = fmaf(ay, inv, a.y);
    float oz = fmaf(az, inv, a.z);
    float ow = fmaf(aw, inv, a.w);
    if (hom_b) {
        const float* bb = het ? het_b : hom_b;
        int bi = 4 * lane - (het ? 64 : 0);
        ox = fmaxf(ox + bb[bi + 0], 0.f);
        oy = fmaxf(oy + bb[bi + 1], 0.f);
        oz = fmaxf(oz + bb[bi + 2], 0.f);
        ow = fmaxf(ow + bb[bi + 3], 0.f);
    }
    *(float4*)&out[(size_t)gw * FDIM + 4 * lane] = make_float4(ox, oy, oz, ow);
}

// ---------------- readout: cat(max_pool, mean_pool) per graph ----------------
__global__ void readout_kernel(const float* __restrict__ h, int accumulate) {
    int g = blockIdx.x;
    int c = threadIdx.x;  // 128 threads = 2H features
    int s = g_gptr[g], e = g_gptr[g + 1];
    float mx = -INFINITY, sm = 0.f;
    for (int n = s; n < e; n++) {
        float v = h[(size_t)n * FDIM + c];
        mx = fmaxf(mx, v);
        sm += v;
    }
    float cnt = fmaxf((float)(e - s), 1.f);
    float mo = (e > s) ? mx : 0.f;
    float ao = sm / cnt;
    if (accumulate) {
        g_r[g * 256 + c] += mo;
        g_r[g * 256 + 128 + c] += ao;
    } else {
        g_r[g * 256 + c] = mo;
        g_r[g * 256 + 128 + c] = ao;
    }
}

// ---------------- MLP head + log_softmax ----------------
__global__ void mlp_kernel(const float* __restrict__ l1W, const float* __restrict__ l1b,
                           const float* __restrict__ l2W, const float* __restrict__ l2b,
                           const float* __restrict__ l3W, const float* __restrict__ l3b,
                           float* __restrict__ out) {
    int g = blockIdx.x;
    int t = threadIdx.x;  // 128 threads
    __shared__ float rs[256];
    __shared__ float z1[128];
    __shared__ float z2[64];
    __shared__ float lg[10];
    rs[t] = g_r[g * 256 + t];
    rs[t + 128] = g_r[g * 256 + 128 + t];
    __syncthreads();
    float acc = l1b[t];
#pragma unroll 8
    for (int k = 0; k < 256; k++) acc = fmaf(rs[k], l1W[k * 128 + t], acc);
    z1[t] = fmaxf(acc, 0.f);
    __syncthreads();
    if (t < 64) {
        float a = l2b[t];
#pragma unroll 8
        for (int k = 0; k < 128; k++) a = fmaf(z1[k], l2W[k * 64 + t], a);
        z2[t] = fmaxf(a, 0.f);
    }
    __syncthreads();
    if (t < 10) {
        float a = l3b[t];
#pragma unroll 8
        for (int k = 0; k < 64; k++) a = fmaf(z2[k], l3W[k * 10 + t], a);
        lg[t] = a;
    }
    __syncthreads();
    if (t == 0) {
        float mx = lg[0];
        for (int i = 1; i < CC; i++) mx = fmaxf(mx, lg[i]);
        float se = 0.f;
        for (int i = 0; i < CC; i++) se += expf(lg[i] - mx);
        float lse = mx + logf(se);
        for (int i = 0; i < CC; i++) out[g * CC + i] = lg[i] - lse;
    }
}

// ---------------- driver ----------------
extern "C" void kernel_launch(void* const* d_in, const int* in_sizes, int n_in,
                              void* d_out, int out_size) {
    const float* x       = (const float*)d_in[0];
    const int*   ei      = (const int*)d_in[1];
    const int*   batch   = (const int*)d_in[2];
    const float* hom_m   = (const float*)d_in[3];
    const float* het_m   = (const float*)d_in[4];
    const float* hom_W   = (const float*)d_in[5];
    const float* hom_b   = (const float*)d_in[6];
    const float* het_W   = (const float*)d_in[7];
    const float* het_b   = (const float*)d_in[8];
    const float* l1W     = (const float*)d_in[9];
    const float* l1b     = (const float*)d_in[10];
    const float* l2W     = (const float*)d_in[11];
    const float* l2b     = (const float*)d_in[12];
    const float* l3W     = (const float*)d_in[13];
    const float* l3b     = (const float*)d_in[14];
    float* out = (float*)d_out;
    (void)in_sizes; (void)n_in; (void)out_size;

    float *T_p, *h_p, *u_p, *W_p;
    cudaGetSymbolAddress((void**)&T_p, g_T);
    cudaGetSymbolAddress((void**)&h_p, g_h);
    cudaGetSymbolAddress((void**)&u_p, g_u);
    cudaGetSymbolAddress((void**)&W_p, g_Wcat);

    // ---- CSR build + weight pack (per call; cheap) ----
    init_zero_kernel<<<(NN + 255) / 256, 256>>>();
    count_kernel<<<(EE + 255) / 256, 256>>>(ei, hom_m, het_m);
    packW_all_kernel<<<(LL * FDIM * TCOLS + 255) / 256, 256>>>(hom_W, het_W);
    scan_kernel<<<1, 1024>>>();
    gptr_kernel<<<(NN + 255) / 256, 256>>>(batch);
    scatter_kernel<<<(EE + 255) / 256, 256>>>(ei, hom_m, het_m);

    const int aggBlocks = (NN * 32 + 255) / 256;
    dim3 gemmGrid(TCOLS / BN, (NN + BM - 1) / BM);

    for (int l = 0; l < LL; l++) {
        const float* hin = (l == 0) ? x : h_p;
        sgemm_tc_kernel<<<gemmGrid, 256>>>(hin, W_p + (size_t)l * FDIM * TCOLS, T_p, NN);

        // hop1 (both views fused): u = A*(h W2) + (h W1)
        agg2_kernel<<<aggBlocks, 256>>>(T_p, TCOLS,
                                        T_p, TCOLS, 128,
                                        nullptr, nullptr,
                                        u_p);
        // hop2 (both views fused): h = relu( A*u + (h W0) + b )
        agg2_kernel<<<aggBlocks, 256>>>(u_p, FDIM,
                                        T_p, TCOLS, 256,
                                        hom_b + l * HDIM, het_b + l * HDIM,
                                        h_p);

        if (l >= 1) readout_kernel<<<GG, FDIM>>>(h_p, (l == 1) ? 0 : 1);
    }

    mlp_kernel<<<GG, 128>>>(l1W, l1b, l2W, l2b, l3W, l3b, out);
}

// round 5
// speedup vs baseline: 1.6956x; 1.6956x over previous
#include <cuda_runtime.h>
#include <cuda_bf16.h>
#include <math.h>
#include <stdint.h>

// Problem constants
#define NN   50000
#define EE   800000
#define FDIM 128
#define HDIM 64
#define LL   3
#define GG   256
#define CC   10
#define TCOLS 384   // 3 n-blocks of 128: [W2(hom|het) | W1(hom|het) | W0(hom|het)]

// ---------------- scratch (__device__ globals; no allocation allowed) ----------------
__device__ float g_T[(size_t)NN * TCOLS];     // per-layer GEMM output [N,384]
__device__ float g_h[(size_t)NN * FDIM];      // node features [N,128] (hom|het)
__device__ float g_u[(size_t)NN * FDIM];      // hop scratch [N,128] (hom|het)
// pre-split bf16 B images: [L][3 nblocks][2 planes][n=128][k=64 words]  (32KB per plane)
__device__ unsigned g_Wbf[LL * 3 * 2 * 8192];

__device__ int    g_cnt[NN];
__device__ int    g_fill[NN];
__device__ int    g_rowptr[NN + 1];
__device__ int    g_blk[256];
__device__ int    g_blkoff[256];
__device__ int    g_csr_src[EE];
__device__ float2 g_csr_mask[EE];             // (hom, het)
__device__ float  g_deg_hom[NN];
__device__ float  g_deg_het[NN];
__device__ int    g_gptr[GG + 1];
__device__ float  g_r[GG * 4 * HDIM];         // readout accumulator [G,256]

// ---------------- CSR build ----------------
__global__ void init_zero_kernel() {
    int i = blockIdx.x * blockDim.x + threadIdx.x;
    if (i < NN) {
        g_cnt[i] = 0;
        g_deg_hom[i] = 0.f;
        g_deg_het[i] = 0.f;
    }
}

__global__ void count_kernel(const int* __restrict__ ei,
                             const float* __restrict__ hm,
                             const float* __restrict__ tm) {
    int e = blockIdx.x * blockDim.x + threadIdx.x;
    if (e >= EE) return;
    int d = ei[EE + e];             // dst row of edge_index
    atomicAdd(&g_cnt[d], 1);
    atomicAdd(&g_deg_hom[d], hm[e]);
    atomicAdd(&g_deg_het[d], tm[e]);
}

// parallel exclusive scan of g_cnt -> g_rowptr/g_fill (3 kernels)
__global__ void blkscan_kernel() {   // grid 196, block 256
    __shared__ int s[256];
    int t = threadIdx.x;
    int i = blockIdx.x * 256 + t;
    int v = (i < NN) ? g_cnt[i] : 0;
    s[t] = v;
    __syncthreads();
#pragma unroll
    for (int off = 1; off < 256; off <<= 1) {
        int x = (t >= off) ? s[t - off] : 0;
        __syncthreads();
        s[t] += x;
        __syncthreads();
    }
    if (i < NN) g_rowptr[i] = s[t] - v;      // exclusive within block
    if (t == 255) g_blk[blockIdx.x] = s[255];
}

__global__ void blkoff_kernel(int nblk) {    // 1 block 256
    __shared__ int s[256];
    int t = threadIdx.x;
    int v = (t < nblk) ? g_blk[t] : 0;
    s[t] = v;
    __syncthreads();
#pragma unroll
    for (int off = 1; off < 256; off <<= 1) {
        int x = (t >= off) ? s[t - off] : 0;
        __syncthreads();
        s[t] += x;
        __syncthreads();
    }
    g_blkoff[t] = s[t] - v;                  // exclusive
}

__global__ void finalize_scan_kernel() {     // grid 196, block 256
    int i = blockIdx.x * blockDim.x + threadIdx.x;
    if (i < NN) {
        int r = g_rowptr[i] + g_blkoff[i >> 8];
        g_rowptr[i] = r;
        g_fill[i] = r;
    }
    if (i == 0) g_rowptr[NN] = EE;
}

__global__ void scatter_kernel(const int* __restrict__ ei,
                               const float* __restrict__ hm,
                               const float* __restrict__ tm) {
    int e = blockIdx.x * blockDim.x + threadIdx.x;
    if (e >= EE) return;
    int d = ei[EE + e];
    int p = atomicAdd(&g_fill[d], 1);
    g_csr_src[p] = ei[e];
    g_csr_mask[p] = make_float2(hm[e], tm[e]);
}

__global__ void gptr_kernel(const int* __restrict__ batch) {
    int n = blockIdx.x * blockDim.x + threadIdx.x;
    if (n >= NN) return;
    int b = batch[n];
    int prev = (n == 0) ? -1 : batch[n - 1];
    for (int g = prev + 1; g <= b; ++g) g_gptr[g] = n;
    if (n == NN - 1) {
        for (int g = b + 1; g <= GG; ++g) g_gptr[g] = NN;
    }
}

// ---------------- bf16 split ----------------
__device__ __forceinline__ void bf_split(float x, unsigned short& h, unsigned short& l) {
    __nv_bfloat16 hb = __float2bfloat16(x);
    float hf = __bfloat162float(hb);
    __nv_bfloat16 lb = __float2bfloat16(x - hf);
    h = __bfloat16_as_ushort(hb);
    l = __bfloat16_as_ushort(lb);
}

// pack all layers' weights: B[n][k] = W_l[hop j][k][col], split hi/lo planes.
// n-block t covers T cols t*128..t*128+127 -> hop j = 2 - t; view = (n>=64)
// thread per (l, t, n, kpair)
__global__ void packWbf_kernel(const float* __restrict__ homW,
                               const float* __restrict__ hetW) {
    int idx = blockIdx.x * blockDim.x + threadIdx.x;
    if (idx >= LL * 3 * 128 * 64) return;
    int kp = idx & 63;
    int n = (idx >> 6) & 127;
    int t = (idx >> 13) % 3;
    int l = idx / (3 * 128 * 64);
    int j = 2 - t;
    int v = (n >> 6) & 1;
    int cc = n & 63;
    const float* Ws = v ? hetW : homW;
    int k0 = 2 * kp;
    float f0 = Ws[((size_t)(l * 3 + j) * FDIM + k0) * HDIM + cc];
    float f1 = Ws[((size_t)(l * 3 + j) * FDIM + k0 + 1) * HDIM + cc];
    unsigned short h0, l0, h1, l1;
    bf_split(f0, h0, l0);
    bf_split(f1, h1, l1);
    unsigned* baseH = &g_Wbf[((size_t)(l * 3 + t) * 2 + 0) * 8192];
    unsigned* baseL = &g_Wbf[((size_t)(l * 3 + t) * 2 + 1) * 8192];
    baseH[n * 64 + kp] = (unsigned)h0 | ((unsigned)h1 << 16);
    baseL[n * 64 + kp] = (unsigned)l0 | ((unsigned)l1 << 16);
}

// ---------------- 3-pass bf16 mma.sync GEMM: C[N,384] = A[N,128] @ W_l ----------------
// grid = 391 (M tiles of 128), 256 threads (8 warps). Warp tile 32x64 (mi=2, ni=8).
// Full K=128 resident in smem (hi+lo planes), loop 3 n-blocks of 128.
// smem rows padded to 68 words (136 halves) -> conflict-free fragment loads.
#define WPAD 68                           // words per row
#define SM_A_WORDS (128 * WPAD)           // 8704 words = 34816 B per plane
#define SM_AHI 0
#define SM_ALO (SM_A_WORDS)
#define SM_BHI (2 * SM_A_WORDS)
#define SM_BLO (3 * SM_A_WORDS)
#define SM_TOTAL_B (4 * SM_A_WORDS * 4)   // 139264 bytes

#define MMA_BF16(d, a0, a1, a2, a3, b0, b1)                                     \
    asm volatile(                                                               \
        "mma.sync.aligned.m16n8k16.row.col.f32.bf16.bf16.f32 "                  \
        "{%0,%1,%2,%3}, {%4,%5,%6,%7}, {%8,%9}, {%0,%1,%2,%3};"                 \
        : "+f"(d[0]), "+f"(d[1]), "+f"(d[2]), "+f"(d[3])                        \
        : "r"(a0), "r"(a1), "r"(a2), "r"(a3), "r"(b0), "r"(b1));

__global__ __launch_bounds__(256, 1) void gemm_bf16_kernel(const float* __restrict__ A,
                                                           const unsigned* __restrict__ Wb,
                                                           float* __restrict__ C) {
    extern __shared__ unsigned sm[];
    const int tid = threadIdx.x;
    const int lane = tid & 31;
    const int wid = tid >> 5;
    const int g = lane >> 2;        // 0..7
    const int tg = lane & 3;        // 0..3
    const int warpRow = (wid & 3) * 32;       // 4 m-warps
    const int warpColB = (wid >> 2) * 64;     // 2 n-warps
    const int mBase = blockIdx.x * 128;

    // ---- convert A tile [128 x 128] f32 -> bf16 hi/lo planes ----
    for (int it = tid; it < 128 * 32; it += 256) {
        int row = it >> 5;
        int c4 = it & 31;                       // float4 index: cols 4c4..4c4+3
        int grow = mBase + row;
        float4 v = make_float4(0.f, 0.f, 0.f, 0.f);
        if (grow < NN) v = *(const float4*)&A[(size_t)grow * FDIM + 4 * c4];
        unsigned short hx, lx, hy, ly, hz, lz, hw, lw;
        bf_split(v.x, hx, lx);
        bf_split(v.y, hy, ly);
        bf_split(v.z, hz, lz);
        bf_split(v.w, hw, lw);
        int w0 = row * WPAD + 2 * c4;
        sm[SM_AHI + w0]     = (unsigned)hx | ((unsigned)hy << 16);
        sm[SM_AHI + w0 + 1] = (unsigned)hz | ((unsigned)hw << 16);
        sm[SM_ALO + w0]     = (unsigned)lx | ((unsigned)ly << 16);
        sm[SM_ALO + w0 + 1] = (unsigned)lz | ((unsigned)lw << 16);
    }
    __syncthreads();

    for (int t = 0; t < 3; t++) {
        // ---- copy B n-block (both planes) into padded smem ----
        {
            const uint4* srcH = (const uint4*)&Wb[(t * 2 + 0) * 8192];
            const uint4* srcL = (const uint4*)&Wb[(t * 2 + 1) * 8192];
            for (int i = tid; i < 128 * 16; i += 256) {
                int r = i >> 4;
                int c = i & 15;                 // uint4 index within row (16 per row)
                *(uint4*)&sm[SM_BHI + r * WPAD + 4 * c] = srcH[r * 16 + c];
                *(uint4*)&sm[SM_BLO + r * WPAD + 4 * c] = srcL[r * 16 + c];
            }
        }
        __syncthreads();

        float acc[2][8][4];
#pragma unroll
        for (int mi = 0; mi < 2; mi++)
#pragma unroll
            for (int ni = 0; ni < 8; ni++)
#pragma unroll
                for (int r = 0; r < 4; r++) acc[mi][ni][r] = 0.f;

#pragma unroll
        for (int ks = 0; ks < 8; ks++) {
            const int kw = ks * 8 + tg;         // word offset within row for this thread
            unsigned ah[2][4], al[2][4];
#pragma unroll
            for (int mi = 0; mi < 2; mi++) {
                int r0 = (warpRow + mi * 16 + g) * WPAD;
                int r1 = r0 + 8 * WPAD;
                ah[mi][0] = sm[SM_AHI + r0 + kw];
                ah[mi][1] = sm[SM_AHI + r1 + kw];
                ah[mi][2] = sm[SM_AHI + r0 + kw + 4];
                ah[mi][3] = sm[SM_AHI + r1 + kw + 4];
                al[mi][0] = sm[SM_ALO + r0 + kw];
                al[mi][1] = sm[SM_ALO + r1 + kw];
                al[mi][2] = sm[SM_ALO + r0 + kw + 4];
                al[mi][3] = sm[SM_ALO + r1 + kw + 4];
            }
#pragma unroll
            for (int ni = 0; ni < 8; ni++) {
                int nrow = (warpColB + ni * 8 + g) * WPAD;
                unsigned bh0 = sm[SM_BHI + nrow + kw];
                unsigned bh1 = sm[SM_BHI + nrow + kw + 4];
                unsigned bl0 = sm[SM_BLO + nrow + kw];
                unsigned bl1 = sm[SM_BLO + nrow + kw + 4];
#pragma unroll
                for (int mi = 0; mi < 2; mi++) {
                    MMA_BF16(acc[mi][ni], ah[mi][0], ah[mi][1], ah[mi][2], ah[mi][3], bh0, bh1);
                    MMA_BF16(acc[mi][ni], al[mi][0], al[mi][1], al[mi][2], al[mi][3], bh0, bh1);
                    MMA_BF16(acc[mi][ni], ah[mi][0], ah[mi][1], ah[mi][2], ah[mi][3], bl0, bl1);
                }
            }
        }

        // ---- epilogue for this n-block ----
#pragma unroll
        for (int mi = 0; mi < 2; mi++) {
            int gr0 = mBase + warpRow + mi * 16 + g;
            int gr1 = gr0 + 8;
#pragma unroll
            for (int ni = 0; ni < 8; ni++) {
                int gc = t * 128 + warpColB + ni * 8 + 2 * tg;
                if (gr0 < NN)
                    *(float2*)&C[(size_t)gr0 * TCOLS + gc] = make_float2(acc[mi][ni][0], acc[mi][ni][1]);
                if (gr1 < NN)
                    *(float2*)&C[(size_t)gr1 * TCOLS + gc] = make_float2(acc[mi][ni][2], acc[mi][ni][3]);
            }
        }
        __syncthreads();
    }
}

// ---------------- fused two-view aggregation: one warp per destination node ----------------
__global__ void agg2_kernel(const float* __restrict__ gather, int gld,
                            const float* __restrict__ add, int ald, int acol,
                            const float* __restrict__ hom_b,  // non-null => relu(.+bias)
                            const float* __restrict__ het_b,
                            float* __restrict__ out) {
    int gw = (blockIdx.x * blockDim.x + threadIdx.x) >> 5;
    int lane = threadIdx.x & 31;
    if (gw >= NN) return;
    const bool het = lane >= 16;
    int s = g_rowptr[gw];
    int e = g_rowptr[gw + 1];
    float ax = 0.f, ay = 0.f, az = 0.f, aw = 0.f;
    for (int i = s; i < e; i++) {
        int sr = g_csr_src[i];
        float2 mm = g_csr_mask[i];
        float m = het ? mm.y : mm.x;
        float4 v = *(const float4*)&gather[(size_t)sr * gld + 4 * lane];
        ax = fmaf(m, v.x, ax);
        ay = fmaf(m, v.y, ay);
        az = fmaf(m, v.z, az);
        aw = fmaf(m, v.w, aw);
    }
    float d = fmaxf(het ? g_deg_het[gw] : g_deg_hom[gw], 1.f);
    float inv = 1.f / d;
    float4 a = *(const float4*)&add[(size_t)gw * ald + acol + 4 * lane];
    float ox = fmaf(ax, inv, a.x);
    float oy = fmaf(ay, inv, a.y);
    float oz = fmaf(az, inv, a.z);
    float ow = fmaf(aw, inv, a.w);
    if (hom_b) {
        const float* bb = het ? het_b : hom_b;
        int bi = 4 * lane - (het ? 64 : 0);
        ox = fmaxf(ox + bb[bi + 0], 0.f);
        oy = fmaxf(oy + bb[bi + 1], 0.f);
        oz = fmaxf(oz + bb[bi + 2], 0.f);
        ow = fmaxf(ow + bb[bi + 3], 0.f);
    }
    *(float4*)&out[(size_t)gw * FDIM + 4 * lane] = make_float4(ox, oy, oz, ow);
}

// ---------------- readout: cat(max_pool, mean_pool) per graph ----------------
__global__ void readout_kernel(const float* __restrict__ h, int accumulate) {
    int g = blockIdx.x;
    int c = threadIdx.x;  // 128 threads = 2H features
    int s = g_gptr[g], e = g_gptr[g + 1];
    float mx = -INFINITY, sm = 0.f;
    for (int n = s; n < e; n++) {
        float v = h[(size_t)n * FDIM + c];
        mx = fmaxf(mx, v);
        sm += v;
    }
    float cnt = fmaxf((float)(e - s), 1.f);
    float mo = (e > s) ? mx : 0.f;
    float ao = sm / cnt;
    if (accumulate) {
        g_r[g * 256 + c] += mo;
        g_r[g * 256 + 128 + c] += ao;
    } else {
        g_r[g * 256 + c] = mo;
        g_r[g * 256 + 128 + c] = ao;
    }
}

// ---------------- MLP head + log_softmax ----------------
__global__ void mlp_kernel(const float* __restrict__ l1W, const float* __restrict__ l1b,
                           const float* __restrict__ l2W, const float* __restrict__ l2b,
                           const float* __restrict__ l3W, const float* __restrict__ l3b,
                           float* __restrict__ out) {
    int g = blockIdx.x;
    int t = threadIdx.x;  // 128 threads
    __shared__ float rs[256];
    __shared__ float z1[128];
    __shared__ float z2[64];
    __shared__ float lg[10];
    rs[t] = g_r[g * 256 + t];
    rs[t + 128] = g_r[g * 256 + 128 + t];
    __syncthreads();
    float acc = l1b[t];
#pragma unroll 8
    for (int k = 0; k < 256; k++) acc = fmaf(rs[k], l1W[k * 128 + t], acc);
    z1[t] = fmaxf(acc, 0.f);
    __syncthreads();
    if (t < 64) {
        float a = l2b[t];
#pragma unroll 8
        for (int k = 0; k < 128; k++) a = fmaf(z1[k], l2W[k * 64 + t], a);
        z2[t] = fmaxf(a, 0.f);
    }
    __syncthreads();
    if (t < 10) {
        float a = l3b[t];
#pragma unroll 8
        for (int k = 0; k < 64; k++) a = fmaf(z2[k], l3W[k * 10 + t], a);
        lg[t] = a;
    }
    __syncthreads();
    if (t == 0) {
        float mx = lg[0];
        for (int i = 1; i < CC; i++) mx = fmaxf(mx, lg[i]);
        float se = 0.f;
        for (int i = 0; i < CC; i++) se += expf(lg[i] - mx);
        float lse = mx + logf(se);
        for (int i = 0; i < CC; i++) out[g * CC + i] = lg[i] - lse;
    }
}

// ---------------- driver ----------------
extern "C" void kernel_launch(void* const* d_in, const int* in_sizes, int n_in,
                              void* d_out, int out_size) {
    const float* x       = (const float*)d_in[0];
    const int*   ei      = (const int*)d_in[1];
    const int*   batch   = (const int*)d_in[2];
    const float* hom_m   = (const float*)d_in[3];
    const float* het_m   = (const float*)d_in[4];
    const float* hom_W   = (const float*)d_in[5];
    const float* hom_b   = (const float*)d_in[6];
    const float* het_W   = (const float*)d_in[7];
    const float* het_b   = (const float*)d_in[8];
    const float* l1W     = (const float*)d_in[9];
    const float* l1b     = (const float*)d_in[10];
    const float* l2W     = (const float*)d_in[11];
    const float* l2b     = (const float*)d_in[12];
    const float* l3W     = (const float*)d_in[13];
    const float* l3b     = (const float*)d_in[14];
    float* out = (float*)d_out;
    (void)in_sizes; (void)n_in; (void)out_size;

    float *T_p, *h_p, *u_p;
    unsigned* Wbf_p;
    cudaGetSymbolAddress((void**)&T_p, g_T);
    cudaGetSymbolAddress((void**)&h_p, g_h);
    cudaGetSymbolAddress((void**)&u_p, g_u);
    cudaGetSymbolAddress((void**)&Wbf_p, g_Wbf);

    static int smem_set = 0;
    if (!smem_set) {
        cudaFuncSetAttribute(gemm_bf16_kernel, cudaFuncAttributeMaxDynamicSharedMemorySize,
                             SM_TOTAL_B);
        smem_set = 1;
    }

    // ---- CSR build + weight pack (per call; cheap) ----
    init_zero_kernel<<<(NN + 255) / 256, 256>>>();
    count_kernel<<<(EE + 255) / 256, 256>>>(ei, hom_m, het_m);
    packWbf_kernel<<<(LL * 3 * 128 * 64 + 255) / 256, 256>>>(hom_W, het_W);
    blkscan_kernel<<<(NN + 255) / 256, 256>>>();
    blkoff_kernel<<<1, 256>>>((NN + 255) / 256);
    finalize_scan_kernel<<<(NN + 255) / 256, 256>>>();
    gptr_kernel<<<(NN + 255) / 256, 256>>>(batch);
    scatter_kernel<<<(EE + 255) / 256, 256>>>(ei, hom_m, het_m);

    const int aggBlocks = (NN * 32 + 255) / 256;
    const int mTiles = (NN + 127) / 128;

    for (int l = 0; l < LL; l++) {
        const float* hin = (l == 0) ? x : h_p;
        gemm_bf16_kernel<<<mTiles, 256, SM_TOTAL_B>>>(hin, Wbf_p + (size_t)l * 3 * 2 * 8192, T_p);

        // hop1 (both views fused): u = A*(h W2) + (h W1)
        agg2_kernel<<<aggBlocks, 256>>>(T_p, TCOLS,
                                        T_p, TCOLS, 128,
                                        nullptr, nullptr,
                                        u_p);
        // hop2 (both views fused): h = relu( A*u + (h W0) + b )
        agg2_kernel<<<aggBlocks, 256>>>(u_p, FDIM,
                                        T_p, TCOLS, 256,
                                        hom_b + l * HDIM, het_b + l * HDIM,
                                        h_p);

        if (l >= 1) readout_kernel<<<GG, FDIM>>>(h_p, (l == 1) ? 0 : 1);
    }

    mlp_kernel<<<GG, 128>>>(l1W, l1b, l2W, l2b, l3W, l3b, out);
}

// round 6
// speedup vs baseline: 1.7728x; 1.0456x over previous
#include <cuda_runtime.h>
#include <cuda_bf16.h>
#include <math.h>
#include <stdint.h>

// Problem constants
#define NN   50000
#define EE   800000
#define FDIM 128
#define HDIM 64
#define LL   3
#define GG   256
#define CC   10
#define TCOLS 384   // 3 n-blocks of 128: [W2(hom|het) | W1(hom|het) | W0(hom|het)]

// ---------------- scratch (__device__ globals; no allocation allowed) ----------------
__device__ float g_T[(size_t)NN * TCOLS];     // per-layer GEMM output [N,384]
__device__ float g_h[(size_t)NN * FDIM];      // node features [N,128] (hom|het)
__device__ float g_u[(size_t)NN * FDIM];      // hop scratch [N,128] (hom|het)
// pre-split bf16 B images: [L][3 nblocks][2 planes][n=128][k=64 words]  (32KB per plane)
__device__ unsigned g_Wbf[LL * 3 * 2 * 8192];

__device__ int    g_cnt[NN];
__device__ int    g_fill[NN];
__device__ int    g_rowptr[NN + 1];
__device__ int    g_blk[256];
__device__ int    g_blkoff[256];
__device__ int    g_csr_src[EE];
__device__ float2 g_csr_mask[EE];             // (hom, het)
__device__ float  g_deg_hom[NN];
__device__ float  g_deg_het[NN];
__device__ int    g_gptr[GG + 1];
__device__ float  g_r[GG * 4 * HDIM];         // readout accumulator [G,256]

// ---------------- CSR build ----------------
__global__ void init_zero_kernel() {
    int i = blockIdx.x * blockDim.x + threadIdx.x;
    if (i < NN) {
        g_cnt[i] = 0;
        g_deg_hom[i] = 0.f;
        g_deg_het[i] = 0.f;
    }
}

__global__ void count_kernel(const int* __restrict__ ei,
                             const float* __restrict__ hm,
                             const float* __restrict__ tm) {
    int e = blockIdx.x * blockDim.x + threadIdx.x;
    if (e >= EE) return;
    int d = ei[EE + e];             // dst row of edge_index
    atomicAdd(&g_cnt[d], 1);
    atomicAdd(&g_deg_hom[d], hm[e]);
    atomicAdd(&g_deg_het[d], tm[e]);
}

// parallel exclusive scan of g_cnt -> g_rowptr/g_fill (3 kernels)
__global__ void blkscan_kernel() {   // grid 196, block 256
    __shared__ int s[256];
    int t = threadIdx.x;
    int i = blockIdx.x * 256 + t;
    int v = (i < NN) ? g_cnt[i] : 0;
    s[t] = v;
    __syncthreads();
#pragma unroll
    for (int off = 1; off < 256; off <<= 1) {
        int x = (t >= off) ? s[t - off] : 0;
        __syncthreads();
        s[t] += x;
        __syncthreads();
    }
    if (i < NN) g_rowptr[i] = s[t] - v;      // exclusive within block
    if (t == 255) g_blk[blockIdx.x] = s[255];
}

__global__ void blkoff_kernel(int nblk) {    // 1 block 256
    __shared__ int s[256];
    int t = threadIdx.x;
    int v = (t < nblk) ? g_blk[t] : 0;
    s[t] = v;
    __syncthreads();
#pragma unroll
    for (int off = 1; off < 256; off <<= 1) {
        int x = (t >= off) ? s[t - off] : 0;
        __syncthreads();
        s[t] += x;
        __syncthreads();
    }
    g_blkoff[t] = s[t] - v;                  // exclusive
}

__global__ void finalize_scan_kernel() {     // grid 196, block 256
    int i = blockIdx.x * blockDim.x + threadIdx.x;
    if (i < NN) {
        int r = g_rowptr[i] + g_blkoff[i >> 8];
        g_rowptr[i] = r;
        g_fill[i] = r;
    }
    if (i == 0) g_rowptr[NN] = EE;
}

__global__ void scatter_kernel(const int* __restrict__ ei,
                               const float* __restrict__ hm,
                               const float* __restrict__ tm) {
    int e = blockIdx.x * blockDim.x + threadIdx.x;
    if (e >= EE) return;
    int d = ei[EE + e];
    int p = atomicAdd(&g_fill[d], 1);
    g_csr_src[p] = ei[e];
    g_csr_mask[p] = make_float2(hm[e], tm[e]);
}

__global__ void gptr_kernel(const int* __restrict__ batch) {
    int n = blockIdx.x * blockDim.x + threadIdx.x;
    if (n >= NN) return;
    int b = batch[n];
    int prev = (n == 0) ? -1 : batch[n - 1];
    for (int g = prev + 1; g <= b; ++g) g_gptr[g] = n;
    if (n == NN - 1) {
        for (int g = b + 1; g <= GG; ++g) g_gptr[g] = NN;
    }
}

// ---------------- bf16 split ----------------
__device__ __forceinline__ void bf_split(float x, unsigned short& h, unsigned short& l) {
    __nv_bfloat16 hb = __float2bfloat16(x);
    float hf = __bfloat162float(hb);
    __nv_bfloat16 lb = __float2bfloat16(x - hf);
    h = __bfloat16_as_ushort(hb);
    l = __bfloat16_as_ushort(lb);
}

// pack all layers' weights: B[n][k] = W_l[hop j][k][col], split hi/lo planes.
// n-block t covers T cols t*128..t*128+127 -> hop j = 2 - t; view = (n>=64)
__global__ void packWbf_kernel(const float* __restrict__ homW,
                               const float* __restrict__ hetW) {
    int idx = blockIdx.x * blockDim.x + threadIdx.x;
    if (idx >= LL * 3 * 128 * 64) return;
    int kp = idx & 63;
    int n = (idx >> 6) & 127;
    int t = (idx >> 13) % 3;
    int l = idx / (3 * 128 * 64);
    int j = 2 - t;
    int v = (n >> 6) & 1;
    int cc = n & 63;
    const float* Ws = v ? hetW : homW;
    int k0 = 2 * kp;
    float f0 = Ws[((size_t)(l * 3 + j) * FDIM + k0) * HDIM + cc];
    float f1 = Ws[((size_t)(l * 3 + j) * FDIM + k0 + 1) * HDIM + cc];
    unsigned short h0, l0, h1, l1;
    bf_split(f0, h0, l0);
    bf_split(f1, h1, l1);
    unsigned* baseH = &g_Wbf[((size_t)(l * 3 + t) * 2 + 0) * 8192];
    unsigned* baseL = &g_Wbf[((size_t)(l * 3 + t) * 2 + 1) * 8192];
    baseH[n * 64 + kp] = (unsigned)h0 | ((unsigned)h1 << 16);
    baseL[n * 64 + kp] = (unsigned)l0 | ((unsigned)l1 << 16);
}

// ---------------- 3-pass bf16 mma.sync GEMM (v2): C[N,384] = A[N,128] @ W_l ----------------
// M tile 64, grid 782, 256 threads (8 warps), 2 CTAs/SM. ldmatrix fragment loads.
// Warp grid: 2 m-warps x 4 n-warps; warp tile 32x32.
#define MTILE 64
#define WPAD 68                            // words per row (stride 4 banks -> ldmatrix conflict-free)
#define SM_AHI 0
#define SM_ALO (MTILE * WPAD)              // 4352
#define SM_BHI (2 * MTILE * WPAD)          // 8704
#define SM_BLO (SM_BHI + 128 * WPAD)       // 17408
#define SM_WORDS (SM_BLO + 128 * WPAD)     // 26112 words = 104448 B

#define MMA_BF16(d, a0, a1, a2, a3, b0, b1)                                     \
    asm volatile(                                                               \
        "mma.sync.aligned.m16n8k16.row.col.f32.bf16.bf16.f32 "                  \
        "{%0,%1,%2,%3}, {%4,%5,%6,%7}, {%8,%9}, {%0,%1,%2,%3};"                 \
        : "+f"(d[0]), "+f"(d[1]), "+f"(d[2]), "+f"(d[3])                        \
        : "r"(a0), "r"(a1), "r"(a2), "r"(a3), "r"(b0), "r"(b1));

__device__ __forceinline__ uint32_t smem_u32(const void* p) {
    uint32_t a;
    asm("{ .reg .u64 t; cvta.to.shared.u64 t, %1; cvt.u32.u64 %0, t; }" : "=r"(a) : "l"(p));
    return a;
}
__device__ __forceinline__ void ldsm_x4(unsigned& r0, unsigned& r1, unsigned& r2, unsigned& r3,
                                        uint32_t addr) {
    asm volatile("ldmatrix.sync.aligned.m8n8.x4.shared.b16 {%0,%1,%2,%3}, [%4];"
                 : "=r"(r0), "=r"(r1), "=r"(r2), "=r"(r3) : "r"(addr));
}
__device__ __forceinline__ void ldsm_x2(unsigned& r0, unsigned& r1, uint32_t addr) {
    asm volatile("ldmatrix.sync.aligned.m8n8.x2.shared.b16 {%0,%1}, [%2];"
                 : "=r"(r0), "=r"(r1) : "r"(addr));
}

__global__ __launch_bounds__(256, 2) void gemm_bf16_kernel(const float* __restrict__ A,
                                                           const unsigned* __restrict__ Wb,
                                                           float* __restrict__ C) {
    extern __shared__ unsigned sm[];
    const uint32_t sbase = smem_u32(sm);
    const int tid = threadIdx.x;
    const int lane = tid & 31;
    const int wid = tid >> 5;
    const int g = lane >> 2;
    const int tg = lane & 3;
    const int warpRow = (wid & 1) * 32;        // 2 m-warps
    const int warpCol = (wid >> 1) * 32;       // 4 n-warps
    const int mBase = blockIdx.x * MTILE;

    // ---- convert A tile [64 x 128] f32 -> bf16 hi/lo planes ----
    for (int it = tid; it < MTILE * 32; it += 256) {
        int row = it >> 5;
        int c4 = it & 31;
        int grow = mBase + row;
        float4 v = make_float4(0.f, 0.f, 0.f, 0.f);
        if (grow < NN) v = *(const float4*)&A[(size_t)grow * FDIM + 4 * c4];
        unsigned short hx, lx, hy, ly, hz, lz, hw, lw;
        bf_split(v.x, hx, lx);
        bf_split(v.y, hy, ly);
        bf_split(v.z, hz, lz);
        bf_split(v.w, hw, lw);
        int w0 = row * WPAD + 2 * c4;
        sm[SM_AHI + w0]     = (unsigned)hx | ((unsigned)hy << 16);
        sm[SM_AHI + w0 + 1] = (unsigned)hz | ((unsigned)hw << 16);
        sm[SM_ALO + w0]     = (unsigned)lx | ((unsigned)ly << 16);
        sm[SM_ALO + w0 + 1] = (unsigned)lz | ((unsigned)lw << 16);
    }
    __syncthreads();

    // ldmatrix lane address components
    const int aRow = (lane & 7) + ((lane >> 3) & 1) * 8;     // fragment row within 16
    const int aWordSel = ((lane >> 4) & 1) * 4;              // k-halfblock select
    const int bLane = lane & 15;
    const int bRow = bLane & 7;
    const int bWordSel = ((bLane >> 3) & 1) * 4;

    for (int t = 0; t < 3; t++) {
        // ---- copy B n-block (both planes) into padded smem ----
        {
            const uint4* srcH = (const uint4*)&Wb[(t * 2 + 0) * 8192];
            const uint4* srcL = (const uint4*)&Wb[(t * 2 + 1) * 8192];
            for (int i = tid; i < 128 * 16; i += 256) {
                int r = i >> 4;
                int c = i & 15;
                *(uint4*)&sm[SM_BHI + r * WPAD + 4 * c] = srcH[r * 16 + c];
                *(uint4*)&sm[SM_BLO + r * WPAD + 4 * c] = srcL[r * 16 + c];
            }
        }
        __syncthreads();

        float acc[2][4][4];
#pragma unroll
        for (int mi = 0; mi < 2; mi++)
#pragma unroll
            for (int ni = 0; ni < 4; ni++)
#pragma unroll
                for (int r = 0; r < 4; r++) acc[mi][ni][r] = 0.f;

#pragma unroll
        for (int ks = 0; ks < 8; ks++) {
            unsigned ah[2][4], al[2][4];
#pragma unroll
            for (int mi = 0; mi < 2; mi++) {
                uint32_t off = (uint32_t)((warpRow + mi * 16 + aRow) * WPAD + 8 * ks + aWordSel) * 4;
                ldsm_x4(ah[mi][0], ah[mi][1], ah[mi][2], ah[mi][3],
                        sbase + SM_AHI * 4 + off);
                ldsm_x4(al[mi][0], al[mi][1], al[mi][2], al[mi][3],
                        sbase + SM_ALO * 4 + off);
            }
            unsigned bh[4][2], bl[4][2];
#pragma unroll
            for (int ni = 0; ni < 4; ni++) {
                uint32_t off = (uint32_t)((warpCol + ni * 8 + bRow) * WPAD + 8 * ks + bWordSel) * 4;
                ldsm_x2(bh[ni][0], bh[ni][1], sbase + SM_BHI * 4 + off);
                ldsm_x2(bl[ni][0], bl[ni][1], sbase + SM_BLO * 4 + off);
            }
#pragma unroll
            for (int ni = 0; ni < 4; ni++)
#pragma unroll
                for (int mi = 0; mi < 2; mi++) {
                    MMA_BF16(acc[mi][ni], ah[mi][0], ah[mi][1], ah[mi][2], ah[mi][3],
                             bh[ni][0], bh[ni][1]);
                    MMA_BF16(acc[mi][ni], al[mi][0], al[mi][1], al[mi][2], al[mi][3],
                             bh[ni][0], bh[ni][1]);
                    MMA_BF16(acc[mi][ni], ah[mi][0], ah[mi][1], ah[mi][2], ah[mi][3],
                             bl[ni][0], bl[ni][1]);
                }
        }

        // ---- epilogue for this n-block ----
#pragma unroll
        for (int mi = 0; mi < 2; mi++) {
            int gr0 = mBase + warpRow + mi * 16 + g;
            int gr1 = gr0 + 8;
#pragma unroll
            for (int ni = 0; ni < 4; ni++) {
                int gc = t * 128 + warpCol + ni * 8 + 2 * tg;
                if (gr0 < NN)
                    *(float2*)&C[(size_t)gr0 * TCOLS + gc] = make_float2(acc[mi][ni][0], acc[mi][ni][1]);
                if (gr1 < NN)
                    *(float2*)&C[(size_t)gr1 * TCOLS + gc] = make_float2(acc[mi][ni][2], acc[mi][ni][3]);
            }
        }
        __syncthreads();
    }
}

// ---------------- fused two-view aggregation: one warp per destination node ----------------
__global__ void agg2_kernel(const float* __restrict__ gather, int gld,
                            const float* __restrict__ add, int ald, int acol,
                            const float* __restrict__ hom_b,  // non-null => relu(.+bias)
                            const float* __restrict__ het_b,
                            float* __restrict__ out) {
    int gw = (blockIdx.x * blockDim.x + threadIdx.x) >> 5;
    int lane = threadIdx.x & 31;
    if (gw >= NN) return;
    const bool het = lane >= 16;
    int s = g_rowptr[gw];
    int e = g_rowptr[gw + 1];
    float ax = 0.f, ay = 0.f, az = 0.f, aw = 0.f;
    for (int i = s; i < e; i++) {
        int sr = g_csr_src[i];
        float2 mm = g_csr_mask[i];
        float m = het ? mm.y : mm.x;
        float4 v = *(const float4*)&gather[(size_t)sr * gld + 4 * lane];
        ax = fmaf(m, v.x, ax);
        ay = fmaf(m, v.y, ay);
        az = fmaf(m, v.z, az);
        aw = fmaf(m, v.w, aw);
    }
    float d = fmaxf(het ? g_deg_het[gw] : g_deg_hom[gw], 1.f);
    float inv = 1.f / d;
    float4 a = *(const float4*)&add[(size_t)gw * ald + acol + 4 * lane];
    float ox = fmaf(ax, inv, a.x);
    float oy = fmaf(ay, inv, a.y);
    float oz = fmaf(az, inv, a.z);
    float ow = fmaf(aw, inv, a.w);
    if (hom_b) {
        const float* bb = het ? het_b : hom_b;
        int bi = 4 * lane - (het ? 64 : 0);
        ox = fmaxf(ox + bb[bi + 0], 0.f);
        oy = fmaxf(oy + bb[bi + 1], 0.f);
        oz = fmaxf(oz + bb[bi + 2], 0.f);
        ow = fmaxf(ow + bb[bi + 3], 0.f);
    }
    *(float4*)&out[(size_t)gw * FDIM + 4 * lane] = make_float4(ox, oy, oz, ow);
}

// ---------------- readout: cat(max_pool, mean_pool) per graph ----------------
__global__ void readout_kernel(const float* __restrict__ h, int accumulate) {
    int g = blockIdx.x;
    int c = threadIdx.x;  // 128 threads = 2H features
    int s = g_gptr[g], e = g_gptr[g + 1];
    float mx = -INFINITY, sm = 0.f;
    for (int n = s; n < e; n++) {
        float v = h[(size_t)n * FDIM + c];
        mx = fmaxf(mx, v);
        sm += v;
    }
    float cnt = fmaxf((float)(e - s), 1.f);
    float mo = (e > s) ? mx : 0.f;
    float ao = sm / cnt;
    if (accumulate) {
        g_r[g * 256 + c] += mo;
        g_r[g * 256 + 128 + c] += ao;
    } else {
        g_r[g * 256 + c] = mo;
        g_r[g * 256 + 128 + c] = ao;
    }
}

// ---------------- MLP head + log_softmax ----------------
__global__ void mlp_kernel(const float* __restrict__ l1W, const float* __restrict__ l1b,
                           const float* __restrict__ l2W, const float* __restrict__ l2b,
                           const float* __restrict__ l3W, const float* __restrict__ l3b,
                           float* __restrict__ out) {
    int g = blockIdx.x;
    int t = threadIdx.x;  // 128 threads
    __shared__ float rs[256];
    __shared__ float z1[128];
    __shared__ float z2[64];
    __shared__ float lg[10];
    rs[t] = g_r[g * 256 + t];
    rs[t + 128] = g_r[g * 256 + 128 + t];
    __syncthreads();
    float acc = l1b[t];
#pragma unroll 8
    for (int k = 0; k < 256; k++) acc = fmaf(rs[k], l1W[k * 128 + t], acc);
    z1[t] = fmaxf(acc, 0.f);
    __syncthreads();
    if (t < 64) {
        float a = l2b[t];
#pragma unroll 8
        for (int k = 0; k < 128; k++) a = fmaf(z1[k], l2W[k * 64 + t], a);
        z2[t] = fmaxf(a, 0.f);
    }
    __syncthreads();
    if (t < 10) {
        float a = l3b[t];
#pragma unroll 8
        for (int k = 0; k < 64; k++) a = fmaf(z2[k], l3W[k * 10 + t], a);
        lg[t] = a;
    }
    __syncthreads();
    if (t == 0) {
        float mx = lg[0];
        for (int i = 1; i < CC; i++) mx = fmaxf(mx, lg[i]);
        float se = 0.f;
        for (int i = 0; i < CC; i++) se += expf(lg[i] - mx);
        float lse = mx + logf(se);
        for (int i = 0; i < CC; i++) out[g * CC + i] = lg[i] - lse;
    }
}

// ---------------- driver ----------------
extern "C" void kernel_launch(void* const* d_in, const int* in_sizes, int n_in,
                              void* d_out, int out_size) {
    const float* x       = (const float*)d_in[0];
    const int*   ei      = (const int*)d_in[1];
    const int*   batch   = (const int*)d_in[2];
    const float* hom_m   = (const float*)d_in[3];
    const float* het_m   = (const float*)d_in[4];
    const float* hom_W   = (const float*)d_in[5];
    const float* hom_b   = (const float*)d_in[6];
    const float* het_W   = (const float*)d_in[7];
    const float* het_b   = (const float*)d_in[8];
    const float* l1W     = (const float*)d_in[9];
    const float* l1b     = (const float*)d_in[10];
    const float* l2W     = (const float*)d_in[11];
    const float* l2b     = (const float*)d_in[12];
    const float* l3W     = (const float*)d_in[13];
    const float* l3b     = (const float*)d_in[14];
    float* out = (float*)d_out;
    (void)in_sizes; (void)n_in; (void)out_size;

    float *T_p, *h_p, *u_p;
    unsigned* Wbf_p;
    cudaGetSymbolAddress((void**)&T_p, g_T);
    cudaGetSymbolAddress((void**)&h_p, g_h);
    cudaGetSymbolAddress((void**)&u_p, g_u);
    cudaGetSymbolAddress((void**)&Wbf_p, g_Wbf);

    cudaFuncSetAttribute(gemm_bf16_kernel, cudaFuncAttributeMaxDynamicSharedMemorySize,
                         SM_WORDS * 4);

    const int aggBlocks = (NN * 32 + 255) / 256;
    const int mTiles = (NN + MTILE - 1) / MTILE;

    // launches 1-3: zero/count/pack; launch 4 = layer-0 GEMM (profiler window)
    init_zero_kernel<<<(NN + 255) / 256, 256>>>();
    count_kernel<<<(EE + 255) / 256, 256>>>(ei, hom_m, het_m);
    packWbf_kernel<<<(LL * 3 * 128 * 64 + 255) / 256, 256>>>(hom_W, het_W);
    gemm_bf16_kernel<<<mTiles, 256, SM_WORDS * 4>>>(x, Wbf_p, T_p);

    // CSR build (independent of the layer-0 GEMM)
    blkscan_kernel<<<(NN + 255) / 256, 256>>>();
    blkoff_kernel<<<1, 256>>>((NN + 255) / 256);
    finalize_scan_kernel<<<(NN + 255) / 256, 256>>>();
    gptr_kernel<<<(NN + 255) / 256, 256>>>(batch);
    scatter_kernel<<<(EE + 255) / 256, 256>>>(ei, hom_m, het_m);

    for (int l = 0; l < LL; l++) {
        if (l > 0)
            gemm_bf16_kernel<<<mTiles, 256, SM_WORDS * 4>>>(h_p, Wbf_p + (size_t)l * 3 * 2 * 8192, T_p);

        // hop1 (both views fused): u = A*(h W2) + (h W1)
        agg2_kernel<<<aggBlocks, 256>>>(T_p, TCOLS,
                                        T_p, TCOLS, 128,
                                        nullptr, nullptr,
                                        u_p);
        // hop2 (both views fused): h = relu( A*u + (h W0) + b )
        agg2_kernel<<<aggBlocks, 256>>>(u_p, FDIM,
                                        T_p, TCOLS, 256,
                                        hom_b + l * HDIM, het_b + l * HDIM,
                                        h_p);

        if (l >= 1) readout_kernel<<<GG, FDIM>>>(h_p, (l == 1) ? 0 : 1);
    }

    mlp_kernel<<<GG, 128>>>(l1W, l1b, l2W, l2b, l3W, l3b, out);
}